// round 8
// baseline (speedup 1.0000x reference)
#include <cuda_runtime.h>
#include <cuda_fp16.h>
#include <cstdint>

#define N_NODES 100000
#define N_EDGES 1600000
#define N_GRAPHS 512

// ---------------- scratch (device globals; no allocation allowed) ----------
__device__ int                g_degi[N_NODES];
__device__ unsigned long long g_edge[N_EDGES];      // packed src | dst<<32
__device__ uint2              g_h1h[N_NODES * 8];   // h1' = (x@W1)*dis, fp16
__device__ uint2              g_agg1h[N_NODES * 8]; // fp16 accumulators
__device__ uint2              g_h2h[N_NODES * 8];   // h2' fp16
__device__ uint2              g_agg2h[N_NODES * 8];
__device__ float              g_gsum[N_GRAPHS];
__device__ float              g_gcnt[N_GRAPHS];
__device__ int                g_done;

// ---------------- f32x2 helpers (Blackwell packed FFMA) ---------------------
__device__ __forceinline__ unsigned long long pack2(float x) {
    unsigned long long r;
    asm("mov.b64 %0, {%1, %1};" : "=l"(r) : "r"(__float_as_uint(x)));
    return r;
}
__device__ __forceinline__ void ffma2(unsigned long long& d,
                                      unsigned long long a,
                                      unsigned long long b) {
    asm("fma.rn.f32x2 %0, %1, %2, %0;" : "+l"(d) : "l"(a), "l"(b));
}
__device__ __forceinline__ float2 unpack2(unsigned long long v) {
    float2 f;
    asm("mov.b64 {%0, %1}, %2;" : "=f"(f.x), "=f"(f.y) : "l"(v));
    return f;
}
__device__ __forceinline__ unsigned h2u(__half2 h) { return *(unsigned*)&h; }
__device__ __forceinline__ float2 u2f2(unsigned u) {
    return __half22float2(*(__half2*)&u);
}

// per-block dtype detection: warp ballot over first 64 u64 words of edge_index
__device__ __forceinline__ int detect_is64(const void* ei) {
    __shared__ int s_is64;
    if (threadIdx.x < 32) {
        const unsigned long long* p = (const unsigned long long*)ei;
        unsigned long long v0 = p[threadIdx.x];
        unsigned long long v1 = p[32 + threadIdx.x];
        unsigned m = __ballot_sync(0xffffffffu,
            (v0 >= (unsigned long long)N_NODES) || (v1 >= (unsigned long long)N_NODES));
        if (threadIdx.x == 0) s_is64 = m ? 0 : 1;
    }
    __syncthreads();
    return s_is64;
}

// ---------------- prep: detect + pack edges + degree hist + zero smalls -----
__global__ void prep_kernel(const void* ei) {
    int is64 = detect_is64(ei);
    if (blockIdx.x == 0) {
        for (int i = threadIdx.x; i < N_GRAPHS; i += 256) {
            g_gsum[i] = 0.f; g_gcnt[i] = 0.f;
        }
        if (threadIdx.x == 0) g_done = 0;
    }
    int e = blockIdx.x * 256 + threadIdx.x;
    if (e >= N_EDGES) return;
    int s, d;
    if (is64) {
        const long long* p = (const long long*)ei;
        s = (int)p[e]; d = (int)p[N_EDGES + e];
    } else {
        const int* p = (const int*)ei;
        s = p[e]; d = p[N_EDGES + e];
    }
    s = min(max(s, 0), N_NODES - 1);
    d = min(max(d, 0), N_NODES - 1);
    g_edge[e] = (unsigned long long)(unsigned)s |
                ((unsigned long long)(unsigned)d << 32);
    atomicAdd(&g_degi[d], 1);
}

// ---------------- gemm1: 256-node x 32-out tile, 4n x 8o per thread ---------
__global__ __launch_bounds__(256) void gemm1_tiled(const float* __restrict__ x,
                                                   const float* __restrict__ W) {
    constexpr int K = 128;
    constexpr int KT = 32;
    constexpr int NPAD = 264;
    __shared__ float Ws[K * 32];
    __shared__ float xs[KT * NPAD];

    int tid = threadIdx.x;
    for (int i = tid; i < K * 8; i += 256)
        ((float4*)Ws)[i] = ((const float4*)W)[i];

    int base = blockIdx.x * 256;
    int tx = tid & 3;
    int ty = tid >> 2;

    unsigned long long acc[4][4];
#pragma unroll
    for (int i = 0; i < 4; i++)
#pragma unroll
        for (int q = 0; q < 4; q++) acc[i][q] = 0ULL;

    int mync = min(base + tid, N_NODES - 1);

#pragma unroll
    for (int kt = 0; kt < K / KT; kt++) {
        const float4* row = (const float4*)(x + (size_t)mync * 128 + kt * KT);
#pragma unroll
        for (int j = 0; j < 8; j++) {
            float4 v = row[j];
            xs[(4 * j + 0) * NPAD + tid] = v.x;
            xs[(4 * j + 1) * NPAD + tid] = v.y;
            xs[(4 * j + 2) * NPAD + tid] = v.z;
            xs[(4 * j + 3) * NPAD + tid] = v.w;
        }
        __syncthreads();
#pragma unroll
        for (int k = 0; k < KT; k++) {
            float4 xv = *(const float4*)&xs[k * NPAD + ty * 4];
            const ulonglong2* wr = (const ulonglong2*)(Ws + (kt * KT + k) * 32 + tx * 8);
            ulonglong2 w0 = wr[0];
            ulonglong2 w1 = wr[1];
            unsigned long long xp0 = pack2(xv.x);
            unsigned long long xp1 = pack2(xv.y);
            unsigned long long xp2 = pack2(xv.z);
            unsigned long long xp3 = pack2(xv.w);
            ffma2(acc[0][0], xp0, w0.x); ffma2(acc[0][1], xp0, w0.y);
            ffma2(acc[0][2], xp0, w1.x); ffma2(acc[0][3], xp0, w1.y);
            ffma2(acc[1][0], xp1, w0.x); ffma2(acc[1][1], xp1, w0.y);
            ffma2(acc[1][2], xp1, w1.x); ffma2(acc[1][3], xp1, w1.y);
            ffma2(acc[2][0], xp2, w0.x); ffma2(acc[2][1], xp2, w0.y);
            ffma2(acc[2][2], xp2, w1.x); ffma2(acc[2][3], xp2, w1.y);
            ffma2(acc[3][0], xp3, w0.x); ffma2(acc[3][1], xp3, w0.y);
            ffma2(acc[3][2], xp3, w1.x); ffma2(acc[3][3], xp3, w1.y);
        }
        __syncthreads();
    }

#pragma unroll
    for (int i = 0; i < 4; i++) {
        int node = base + ty * 4 + i;
        if (node >= N_NODES) break;
        float dis = rsqrtf((float)g_degi[node] + 1.0f);
        float2 p0 = unpack2(acc[i][0]);
        float2 p1 = unpack2(acc[i][1]);
        float2 p2 = unpack2(acc[i][2]);
        float2 p3 = unpack2(acc[i][3]);
        uint4 t;
        t.x = h2u(__floats2half2_rn(p0.x * dis, p0.y * dis));
        t.y = h2u(__floats2half2_rn(p1.x * dis, p1.y * dis));
        t.z = h2u(__floats2half2_rn(p2.x * dis, p2.y * dis));
        t.w = h2u(__floats2half2_rn(p3.x * dis, p3.y * dis));
        *(uint4*)(g_h1h + (size_t)node * 8 + tx * 2) = t;
        uint4 z; z.x = 0u; z.y = 0u; z.z = 0u; z.w = 0u;
        *(uint4*)(g_agg1h + (size_t)node * 8 + tx * 2) = z;
    }
}

// ---------------- gemm2: 512 threads, 256-node tile, 2n x 8o per thread -----
// in = relu(dis*(agg1+h1')+b1); h2' = (in@W2)*dis; zero agg2
__global__ __launch_bounds__(512) void gemm2_tiled(const float* __restrict__ W,
                                                   const float* __restrict__ b1) {
    constexpr int NPAD = 264;
    __shared__ float Ws[32 * 32];
    __shared__ float xs[32 * NPAD];

    int tid = threadIdx.x;
    for (int i = tid; i < 32 * 8; i += 512)
        ((float4*)Ws)[i] = ((const float4*)W)[i];

    int base = blockIdx.x * 256;

    // staging: 512 threads; thread handles half a node-row (16 k-values)
    {
        int nl = tid & 255;
        int kh = tid >> 8;                 // 0 or 1
        int node = min(base + nl, N_NODES - 1);
        float disn = rsqrtf((float)g_degi[node] + 1.0f);
        const uint4* aggp = (const uint4*)(g_agg1h + (size_t)node * 8) + kh * 2;
        const uint4* hp   = (const uint4*)(g_h1h  + (size_t)node * 8) + kh * 2;
        uint4 av0 = aggp[0], av1 = aggp[1];
        uint4 hv0 = hp[0],   hv1 = hp[1];
#pragma unroll
        for (int u = 0; u < 2; u++) {
            uint4 av = u ? av1 : av0;
            uint4 hv = u ? hv1 : hv0;
            int c0 = kh * 16 + u * 8;
            float2 a0 = u2f2(av.x), a1 = u2f2(av.y), a2 = u2f2(av.z), a3 = u2f2(av.w);
            float2 h0 = u2f2(hv.x), h1v = u2f2(hv.y), h2v = u2f2(hv.z), h3 = u2f2(hv.w);
            float4 bA = ((const float4*)b1)[c0 / 4];
            float4 bB = ((const float4*)b1)[c0 / 4 + 1];
            xs[(c0 + 0) * NPAD + nl] = fmaxf(fmaf(disn, a0.x + h0.x,  bA.x), 0.f);
            xs[(c0 + 1) * NPAD + nl] = fmaxf(fmaf(disn, a0.y + h0.y,  bA.y), 0.f);
            xs[(c0 + 2) * NPAD + nl] = fmaxf(fmaf(disn, a1.x + h1v.x, bA.z), 0.f);
            xs[(c0 + 3) * NPAD + nl] = fmaxf(fmaf(disn, a1.y + h1v.y, bA.w), 0.f);
            xs[(c0 + 4) * NPAD + nl] = fmaxf(fmaf(disn, a2.x + h2v.x, bB.x), 0.f);
            xs[(c0 + 5) * NPAD + nl] = fmaxf(fmaf(disn, a2.y + h2v.y, bB.y), 0.f);
            xs[(c0 + 6) * NPAD + nl] = fmaxf(fmaf(disn, a3.x + h3.x,  bB.z), 0.f);
            xs[(c0 + 7) * NPAD + nl] = fmaxf(fmaf(disn, a3.y + h3.y,  bB.w), 0.f);
        }
    }
    __syncthreads();

    // compute: tx = outs group, ty = node pair
    int tx = tid & 3;
    int ty = tid >> 2;       // 0..127 -> nodes base + ty*2 .. +2

    unsigned long long acc[2][4];
#pragma unroll
    for (int i = 0; i < 2; i++)
#pragma unroll
        for (int q = 0; q < 4; q++) acc[i][q] = 0ULL;

#pragma unroll
    for (int k = 0; k < 32; k++) {
        float2 xv = *(const float2*)&xs[k * NPAD + ty * 2];
        const ulonglong2* wr = (const ulonglong2*)(Ws + k * 32 + tx * 8);
        ulonglong2 w0 = wr[0];
        ulonglong2 w1 = wr[1];
        unsigned long long xp0 = pack2(xv.x);
        unsigned long long xp1 = pack2(xv.y);
        ffma2(acc[0][0], xp0, w0.x); ffma2(acc[0][1], xp0, w0.y);
        ffma2(acc[0][2], xp0, w1.x); ffma2(acc[0][3], xp0, w1.y);
        ffma2(acc[1][0], xp1, w0.x); ffma2(acc[1][1], xp1, w0.y);
        ffma2(acc[1][2], xp1, w1.x); ffma2(acc[1][3], xp1, w1.y);
    }

#pragma unroll
    for (int i = 0; i < 2; i++) {
        int node = base + ty * 2 + i;
        if (node >= N_NODES) break;
        float dis = rsqrtf((float)g_degi[node] + 1.0f);
        float2 p0 = unpack2(acc[i][0]);
        float2 p1 = unpack2(acc[i][1]);
        float2 p2 = unpack2(acc[i][2]);
        float2 p3 = unpack2(acc[i][3]);
        uint4 t;
        t.x = h2u(__floats2half2_rn(p0.x * dis, p0.y * dis));
        t.y = h2u(__floats2half2_rn(p1.x * dis, p1.y * dis));
        t.z = h2u(__floats2half2_rn(p2.x * dis, p2.y * dis));
        t.w = h2u(__floats2half2_rn(p3.x * dis, p3.y * dis));
        *(uint4*)(g_h2h + (size_t)node * 8 + tx * 2) = t;
        uint4 z; z.x = 0u; z.y = 0u; z.z = 0u; z.w = 0u;
        *(uint4*)(g_agg2h + (size_t)node * 8 + tx * 2) = z;
    }
}

// ---------------- edge scatter: agg[dst] += h'[src] (all fp16), MLP=8 -------
template <int LAYER>
__global__ __launch_bounds__(256) void scatter_kernel() {
    const uint2* h = (LAYER == 1) ? g_h1h : g_h2h;
    uint2* agg = (LAYER == 1) ? g_agg1h : g_agg2h;
    const int Q = N_EDGES / 8;

    int idx = blockIdx.x * 256 + threadIdx.x;
    int e0 = idx >> 3;
    if (e0 >= Q) return;
    int c = idx & 7;

    unsigned long long ed[8];
#pragma unroll
    for (int j = 0; j < 8; j++) ed[j] = g_edge[e0 + j * Q];

    uint2 v[8];
#pragma unroll
    for (int j = 0; j < 8; j++)
        v[j] = h[(size_t)(unsigned)(ed[j] & 0xffffffffu) * 8 + c];

#pragma unroll
    for (int j = 0; j < 8; j++) {
        uint2* p = agg + (size_t)(unsigned)(ed[j] >> 32) * 8 + c;
        asm volatile("red.global.add.noftz.v2.f16x2 [%0], {%1,%2};"
                     :: "l"(p), "r"(v[j].x), "r"(v[j].y)
                     : "memory");
    }
}

// ---------------- pool: 4 threads/node, shfl reduce, + final ----------------
__global__ void pool_kernel(const void* ei, const void* batch,
                            const float* __restrict__ b2,
                            const float* __restrict__ Wo,
                            const float* __restrict__ bo,
                            float* __restrict__ out) {
    int is64 = detect_is64(ei);
    int idx = blockIdx.x * 256 + threadIdx.x;
    int n = idx >> 2;
    int q = idx & 3;
    if (n < N_NODES) {
        float dis = rsqrtf((float)g_degi[n] + 1.0f);
        uint4 av = ((const uint4*)(g_agg2h + (size_t)n * 8))[q];
        uint4 hv = ((const uint4*)(g_h2h + (size_t)n * 8))[q];
        float4 bA = ((const float4*)b2)[q * 2];
        float4 bB = ((const float4*)b2)[q * 2 + 1];
        float4 wA = ((const float4*)Wo)[q * 2];
        float4 wB = ((const float4*)Wo)[q * 2 + 1];
        float2 a0 = u2f2(av.x), a1 = u2f2(av.y), a2 = u2f2(av.z), a3 = u2f2(av.w);
        float2 h0 = u2f2(hv.x), h1v = u2f2(hv.y), h2v = u2f2(hv.z), h3 = u2f2(hv.w);
        float s = 0.f;
        s += fmaxf(fmaf(dis, a0.x + h0.x,  bA.x), 0.f) * wA.x;
        s += fmaxf(fmaf(dis, a0.y + h0.y,  bA.y), 0.f) * wA.y;
        s += fmaxf(fmaf(dis, a1.x + h1v.x, bA.z), 0.f) * wA.z;
        s += fmaxf(fmaf(dis, a1.y + h1v.y, bA.w), 0.f) * wA.w;
        s += fmaxf(fmaf(dis, a2.x + h2v.x, bB.x), 0.f) * wB.x;
        s += fmaxf(fmaf(dis, a2.y + h2v.y, bB.y), 0.f) * wB.y;
        s += fmaxf(fmaf(dis, a3.x + h3.x,  bB.z), 0.f) * wB.z;
        s += fmaxf(fmaf(dis, a3.y + h3.y,  bB.w), 0.f) * wB.w;
        // reduce across the 4 lanes of this node
        s += __shfl_xor_sync(0xffffffffu, s, 1);
        s += __shfl_xor_sync(0xffffffffu, s, 2);
        if (q == 0) {
            int g;
            if (is64) g = (int)((const long long*)batch)[n];
            else      g = ((const int*)batch)[n];
            g = min(max(g, 0), N_GRAPHS - 1);
            atomicAdd(&g_gsum[g], s);
            atomicAdd(&g_gcnt[g], 1.0f);
        }
    }

    // last-block finalize
    __threadfence();
    __syncthreads();
    __shared__ int s_last;
    if (threadIdx.x == 0) {
        int t = atomicAdd(&g_done, 1);
        s_last = (t == (int)gridDim.x - 1) ? 1 : 0;
    }
    __syncthreads();
    if (s_last) {
        float bias = bo[0];
        for (int i = threadIdx.x; i < N_GRAPHS; i += 256) {
            float sv = atomicAdd(&g_gsum[i], 0.0f);   // coherent read
            float cv = atomicAdd(&g_gcnt[i], 0.0f);
            out[i] = sv / fmaxf(cv, 1.0f) + bias;
        }
        __syncthreads();
        if (threadIdx.x == 0) g_done = 0;   // self-reset for graph replay
    }
}

// ---------------- launch ----------------------------------------------------
extern "C" void kernel_launch(void* const* d_in, const int* in_sizes, int n_in,
                              void* d_out, int out_size) {
    const float* x   = (const float*)d_in[0];
    const void*  ei  = d_in[1];
    const void*  bat = d_in[2];
    const float* W1  = (const float*)d_in[3];
    const float* b1  = (const float*)d_in[4];
    const float* W2  = (const float*)d_in[5];
    const float* b2  = (const float*)d_in[6];
    const float* Wo  = (const float*)d_in[7];
    const float* bo  = (const float*)d_in[8];
    float* out = (float*)d_out;

    void* p_degi = nullptr;
    cudaGetSymbolAddress(&p_degi, g_degi);
    cudaMemsetAsync(p_degi, 0, N_NODES * sizeof(int));

    prep_kernel<<<(N_EDGES + 255) / 256, 256>>>(ei);

    const int GB = (N_NODES + 255) / 256;   // 391

    // layer 1
    gemm1_tiled<<<GB, 256>>>(x, W1);
    scatter_kernel<1><<<(N_EDGES + 255) / 256, 256>>>();

    // layer 2
    gemm2_tiled<<<GB, 512>>>(W2, b1);
    scatter_kernel<2><<<(N_EDGES + 255) / 256, 256>>>();

    // pooling + head (final fold via last-block)
    pool_kernel<<<(N_NODES * 4 + 255) / 256, 256>>>(ei, bat, b2, Wo, bo, out);
}

// round 10
// speedup vs baseline: 1.0293x; 1.0293x over previous
#include <cuda_runtime.h>
#include <cuda_fp16.h>
#include <cstdint>

#define N_NODES 100000
#define N_EDGES 1600000
#define N_GRAPHS 512

// ---------------- scratch (device globals; no allocation allowed) ----------
__device__ int                g_degi[N_NODES];
__device__ unsigned long long g_edge[N_EDGES];      // packed src | dst<<32
__device__ uint2              g_h1h[N_NODES * 8];   // h1' = (x@W1)*dis, fp16
__device__ uint2              g_agg1h[N_NODES * 8]; // fp16 accumulators
__device__ uint2              g_h2h[N_NODES * 8];   // h2' fp16
__device__ uint2              g_agg2h[N_NODES * 8];
__device__ float              g_gsum[N_GRAPHS];
__device__ float              g_gcnt[N_GRAPHS];
__device__ int                g_done;

// ---------------- f32x2 helpers (Blackwell packed FFMA) ---------------------
__device__ __forceinline__ unsigned long long pack2(float x) {
    unsigned long long r;
    asm("mov.b64 %0, {%1, %1};" : "=l"(r) : "r"(__float_as_uint(x)));
    return r;
}
__device__ __forceinline__ void ffma2(unsigned long long& d,
                                      unsigned long long a,
                                      unsigned long long b) {
    asm("fma.rn.f32x2 %0, %1, %2, %0;" : "+l"(d) : "l"(a), "l"(b));
}
__device__ __forceinline__ float2 unpack2(unsigned long long v) {
    float2 f;
    asm("mov.b64 {%0, %1}, %2;" : "=f"(f.x), "=f"(f.y) : "l"(v));
    return f;
}
__device__ __forceinline__ unsigned h2u(__half2 h) { return *(unsigned*)&h; }
__device__ __forceinline__ float2 u2f2(unsigned u) {
    return __half22float2(*(__half2*)&u);
}

// per-block dtype detection: warp ballot over first 64 u64 words of edge_index
__device__ __forceinline__ int detect_is64(const void* ei) {
    __shared__ int s_is64;
    if (threadIdx.x < 32) {
        const unsigned long long* p = (const unsigned long long*)ei;
        unsigned long long v0 = p[threadIdx.x];
        unsigned long long v1 = p[32 + threadIdx.x];
        unsigned m = __ballot_sync(0xffffffffu,
            (v0 >= (unsigned long long)N_NODES) || (v1 >= (unsigned long long)N_NODES));
        if (threadIdx.x == 0) s_is64 = m ? 0 : 1;
    }
    __syncthreads();
    return s_is64;
}

// ---------------- prep: detect + pack edges + degree hist + zero smalls -----
__global__ void prep_kernel(const void* ei) {
    int is64 = detect_is64(ei);
    if (blockIdx.x == 0) {
        for (int i = threadIdx.x; i < N_GRAPHS; i += 256) {
            g_gsum[i] = 0.f; g_gcnt[i] = 0.f;
        }
        if (threadIdx.x == 0) g_done = 0;
    }
    int e = blockIdx.x * 256 + threadIdx.x;
    if (e >= N_EDGES) return;
    int s, d;
    if (is64) {
        const long long* p = (const long long*)ei;
        s = (int)p[e]; d = (int)p[N_EDGES + e];
    } else {
        const int* p = (const int*)ei;
        s = p[e]; d = p[N_EDGES + e];
    }
    s = min(max(s, 0), N_NODES - 1);
    d = min(max(d, 0), N_NODES - 1);
    g_edge[e] = (unsigned long long)(unsigned)s |
                ((unsigned long long)(unsigned)d << 32);
    atomicAdd(&g_degi[d], 1);
}

// ---------------- tiled GEMM: 256-node x 32-out tile, 4n x 8o per thread ----
// LAYER 1: in = x (f32 global, K=128)      -> h1' = (in@W1)*dis fp16, zero agg1
// LAYER 2: in = relu(dis*(agg1+h1')+b1)    -> h2' = (in@W2)*dis fp16, zero agg2
template <int K, int LAYER>
__global__ __launch_bounds__(256) void gemm_tiled(const float* __restrict__ x,
                                                  const float* __restrict__ W,
                                                  const float* __restrict__ b1) {
    constexpr int KT = 32;
    constexpr int NPAD = 264;   // 264%32=8 -> conflict-free transpose stores
    __shared__ float Ws[K * 32];
    __shared__ float xs[KT * NPAD];

    int tid = threadIdx.x;
    for (int i = tid; i < K * 8; i += 256)
        ((float4*)Ws)[i] = ((const float4*)W)[i];

    int base = blockIdx.x * 256;
    int tx = tid & 3;          // out-group: outs [tx*8, tx*8+8)
    int ty = tid >> 2;         // node-group: nodes base+ty*4 .. +4

    unsigned long long acc[4][4];
#pragma unroll
    for (int i = 0; i < 4; i++)
#pragma unroll
        for (int q = 0; q < 4; q++) acc[i][q] = 0ULL;

    int mync = min(base + tid, N_NODES - 1);   // clamped staging node

#pragma unroll
    for (int kt = 0; kt < K / KT; kt++) {
        // ---- stage k-transposed input tile ----
        if (LAYER == 1) {
            const float4* row = (const float4*)(x + (size_t)mync * 128 + kt * KT);
#pragma unroll
            for (int j = 0; j < 8; j++) {
                float4 v = row[j];
                xs[(4 * j + 0) * NPAD + tid] = v.x;
                xs[(4 * j + 1) * NPAD + tid] = v.y;
                xs[(4 * j + 2) * NPAD + tid] = v.z;
                xs[(4 * j + 3) * NPAD + tid] = v.w;
            }
        } else {
            float dis = rsqrtf((float)g_degi[mync] + 1.0f);
            const uint2* aggp = g_agg1h + (size_t)mync * 8;
            const uint2* hp = g_h1h + (size_t)mync * 8;
#pragma unroll
            for (int cq = 0; cq < 8; cq++) {
                uint2 av = aggp[cq], hv = hp[cq];
                float2 a01 = u2f2(av.x), a23 = u2f2(av.y);
                float2 h01 = u2f2(hv.x), h23 = u2f2(hv.y);
                float4 b = ((const float4*)b1)[cq];
                xs[(4 * cq + 0) * NPAD + tid] = fmaxf(fmaf(dis, a01.x + h01.x, b.x), 0.f);
                xs[(4 * cq + 1) * NPAD + tid] = fmaxf(fmaf(dis, a01.y + h01.y, b.y), 0.f);
                xs[(4 * cq + 2) * NPAD + tid] = fmaxf(fmaf(dis, a23.x + h23.x, b.z), 0.f);
                xs[(4 * cq + 3) * NPAD + tid] = fmaxf(fmaf(dis, a23.y + h23.y, b.w), 0.f);
            }
        }
        __syncthreads();

        // ---- compute ----
#pragma unroll
        for (int k = 0; k < KT; k++) {
            float4 xv = *(const float4*)&xs[k * NPAD + ty * 4];
            const ulonglong2* wr = (const ulonglong2*)(Ws + (kt * KT + k) * 32 + tx * 8);
            ulonglong2 w0 = wr[0];
            ulonglong2 w1 = wr[1];
            unsigned long long xp0 = pack2(xv.x);
            unsigned long long xp1 = pack2(xv.y);
            unsigned long long xp2 = pack2(xv.z);
            unsigned long long xp3 = pack2(xv.w);
            ffma2(acc[0][0], xp0, w0.x); ffma2(acc[0][1], xp0, w0.y);
            ffma2(acc[0][2], xp0, w1.x); ffma2(acc[0][3], xp0, w1.y);
            ffma2(acc[1][0], xp1, w0.x); ffma2(acc[1][1], xp1, w0.y);
            ffma2(acc[1][2], xp1, w1.x); ffma2(acc[1][3], xp1, w1.y);
            ffma2(acc[2][0], xp2, w0.x); ffma2(acc[2][1], xp2, w0.y);
            ffma2(acc[2][2], xp2, w1.x); ffma2(acc[2][3], xp2, w1.y);
            ffma2(acc[3][0], xp3, w0.x); ffma2(acc[3][1], xp3, w0.y);
            ffma2(acc[3][2], xp3, w1.x); ffma2(acc[3][3], xp3, w1.y);
        }
        __syncthreads();
    }

    // ---- epilogue: scale by dis, convert fp16, write h + zero agg ----
    uint2* hout = (LAYER == 1) ? g_h1h : g_h2h;
    uint2* aggout = (LAYER == 1) ? g_agg1h : g_agg2h;
#pragma unroll
    for (int i = 0; i < 4; i++) {
        int node = base + ty * 4 + i;
        if (node >= N_NODES) break;
        float dis = rsqrtf((float)g_degi[node] + 1.0f);
        float2 p0 = unpack2(acc[i][0]);
        float2 p1 = unpack2(acc[i][1]);
        float2 p2 = unpack2(acc[i][2]);
        float2 p3 = unpack2(acc[i][3]);
        uint4 t;
        t.x = h2u(__floats2half2_rn(p0.x * dis, p0.y * dis));
        t.y = h2u(__floats2half2_rn(p1.x * dis, p1.y * dis));
        t.z = h2u(__floats2half2_rn(p2.x * dis, p2.y * dis));
        t.w = h2u(__floats2half2_rn(p3.x * dis, p3.y * dis));
        *(uint4*)(hout + (size_t)node * 8 + tx * 2) = t;
        uint4 z; z.x = 0u; z.y = 0u; z.z = 0u; z.w = 0u;
        *(uint4*)(aggout + (size_t)node * 8 + tx * 2) = z;
    }
}

// ---------------- edge scatter: agg[dst] += h'[src] (fp16, 16B red) ----------
// 4 lanes per edge (16B each via v4.f16x2); 4 independent edges/thread (MLP=4)
template <int LAYER>
__global__ __launch_bounds__(256) void scatter_kernel() {
    const uint4* h = (LAYER == 1) ? (const uint4*)g_h1h : (const uint4*)g_h2h;
    uint4* agg = (LAYER == 1) ? (uint4*)g_agg1h : (uint4*)g_agg2h;
    const int Q = N_EDGES / 4;

    int idx = blockIdx.x * 256 + threadIdx.x;
    int e0 = idx >> 2;
    if (e0 >= Q) return;
    int c = idx & 3;   // quarter-row: 16B = 1 uint4

    unsigned long long ed[4];
#pragma unroll
    for (int j = 0; j < 4; j++) ed[j] = g_edge[e0 + j * Q];

    uint4 v[4];
#pragma unroll
    for (int j = 0; j < 4; j++)
        v[j] = h[(size_t)(unsigned)(ed[j] & 0xffffffffu) * 4 + c];

#pragma unroll
    for (int j = 0; j < 4; j++) {
        uint4* p = agg + (size_t)(unsigned)(ed[j] >> 32) * 4 + c;
        asm volatile("red.global.add.noftz.v4.f16x2 [%0], {%1,%2,%3,%4};"
                     :: "l"(p), "r"(v[j].x), "r"(v[j].y), "r"(v[j].z), "r"(v[j].w)
                     : "memory");
    }
}

// ---------------- pool: relu2 + bias + dot(Wo) + segment sums + final -------
__global__ void pool_kernel(const void* ei, const void* batch,
                            const float* __restrict__ b2,
                            const float* __restrict__ Wo,
                            const float* __restrict__ bo,
                            float* __restrict__ out) {
    int is64 = detect_is64(ei);
    int n = blockIdx.x * 256 + threadIdx.x;
    if (n < N_NODES) {
        int g;
        if (is64) g = (int)((const long long*)batch)[n];
        else      g = ((const int*)batch)[n];
        g = min(max(g, 0), N_GRAPHS - 1);
        float dis = rsqrtf((float)g_degi[n] + 1.0f);
        const uint2* a2 = g_agg2h + (size_t)n * 8;
        const uint2* hh = g_h2h + (size_t)n * 8;
        float s = 0.f;
#pragma unroll
        for (int c = 0; c < 8; c++) {
            uint2 av = a2[c];
            uint2 hv = hh[c];
            float2 a01 = u2f2(av.x), a23 = u2f2(av.y);
            float2 h01 = u2f2(hv.x), h23 = u2f2(hv.y);
            float4 b = ((const float4*)b2)[c];
            float4 w = ((const float4*)Wo)[c];
            s += fmaxf(fmaf(dis, a01.x + h01.x, b.x), 0.f) * w.x;
            s += fmaxf(fmaf(dis, a01.y + h01.y, b.y), 0.f) * w.y;
            s += fmaxf(fmaf(dis, a23.x + h23.x, b.z), 0.f) * w.z;
            s += fmaxf(fmaf(dis, a23.y + h23.y, b.w), 0.f) * w.w;
        }
        atomicAdd(&g_gsum[g], s);
        atomicAdd(&g_gcnt[g], 1.0f);
    }

    // last-block finalize
    __threadfence();
    __syncthreads();
    __shared__ int s_last;
    if (threadIdx.x == 0) {
        int t = atomicAdd(&g_done, 1);
        s_last = (t == (int)gridDim.x - 1) ? 1 : 0;
    }
    __syncthreads();
    if (s_last) {
        float bias = bo[0];
        for (int i = threadIdx.x; i < N_GRAPHS; i += 256) {
            float sv = atomicAdd(&g_gsum[i], 0.0f);   // coherent read
            float cv = atomicAdd(&g_gcnt[i], 0.0f);
            out[i] = sv / fmaxf(cv, 1.0f) + bias;
        }
        __syncthreads();
        if (threadIdx.x == 0) g_done = 0;   // self-reset for graph replay
    }
}

// ---------------- launch ----------------------------------------------------
extern "C" void kernel_launch(void* const* d_in, const int* in_sizes, int n_in,
                              void* d_out, int out_size) {
    const float* x   = (const float*)d_in[0];
    const void*  ei  = d_in[1];
    const void*  bat = d_in[2];
    const float* W1  = (const float*)d_in[3];
    const float* b1  = (const float*)d_in[4];
    const float* W2  = (const float*)d_in[5];
    const float* b2  = (const float*)d_in[6];
    const float* Wo  = (const float*)d_in[7];
    const float* bo  = (const float*)d_in[8];
    float* out = (float*)d_out;

    void* p_degi = nullptr;
    cudaGetSymbolAddress(&p_degi, g_degi);
    cudaMemsetAsync(p_degi, 0, N_NODES * sizeof(int));

    prep_kernel<<<(N_EDGES + 255) / 256, 256>>>(ei);

    const int GB = (N_NODES + 255) / 256;   // 391

    // layer 1
    gemm_tiled<128, 1><<<GB, 256>>>(x, W1, b1);
    scatter_kernel<1><<<(N_EDGES + 255) / 256, 256>>>();

    // layer 2 (fuse1 folded into gemm2 staging)
    gemm_tiled<32, 2><<<GB, 256>>>(x, W2, b1);
    scatter_kernel<2><<<(N_EDGES + 255) / 256, 256>>>();

    // pooling + head (final fold via last-block)
    pool_kernel<<<(N_NODES + 255) / 256, 256>>>(ei, bat, b2, Wo, bo, out);
}

// round 11
// speedup vs baseline: 1.0721x; 1.0417x over previous
#include <cuda_runtime.h>
#include <cuda_fp16.h>
#include <cstdint>

#define N_NODES 100000
#define N_EDGES 1600000
#define N_GRAPHS 512

// ---------------- scratch (device globals; no allocation allowed) ----------
__device__ int                g_degi[N_NODES];
__device__ __half             g_dish[N_NODES];     // dis = rsqrt(deg+1), fp16
__device__ unsigned long long g_edge[N_EDGES];     // packed src | dst<<32
__device__ uint2              g_h1h[N_NODES * 8];  // h1 = x@W1 (UNSCALED), fp16
__device__ uint2              g_agg1h[N_NODES * 8];// fp16 accumulators
__device__ uint2              g_h2h[N_NODES * 8];  // h2' = (in@W2)*dis, fp16
__device__ uint2              g_agg2h[N_NODES * 8];
__device__ float              g_gsum[N_GRAPHS];
__device__ float              g_gcnt[N_GRAPHS];
__device__ int                g_done;

// ---------------- f32x2 helpers (Blackwell packed FFMA) ---------------------
__device__ __forceinline__ unsigned long long pack2(float x) {
    unsigned long long r;
    asm("mov.b64 %0, {%1, %1};" : "=l"(r) : "r"(__float_as_uint(x)));
    return r;
}
__device__ __forceinline__ void ffma2(unsigned long long& d,
                                      unsigned long long a,
                                      unsigned long long b) {
    asm("fma.rn.f32x2 %0, %1, %2, %0;" : "+l"(d) : "l"(a), "l"(b));
}
__device__ __forceinline__ float2 unpack2(unsigned long long v) {
    float2 f;
    asm("mov.b64 {%0, %1}, %2;" : "=f"(f.x), "=f"(f.y) : "l"(v));
    return f;
}
__device__ __forceinline__ unsigned h2u(__half2 h) { return *(unsigned*)&h; }
__device__ __forceinline__ __half2 u2h2(unsigned u) { return *(__half2*)&u; }
__device__ __forceinline__ float2 u2f2(unsigned u) {
    return __half22float2(*(__half2*)&u);
}

// per-block dtype detection: warp ballot over first 64 u64 words of edge_index
__device__ __forceinline__ int detect_is64(const void* ei) {
    __shared__ int s_is64;
    if (threadIdx.x < 32) {
        const unsigned long long* p = (const unsigned long long*)ei;
        unsigned long long v0 = p[threadIdx.x];
        unsigned long long v1 = p[32 + threadIdx.x];
        unsigned m = __ballot_sync(0xffffffffu,
            (v0 >= (unsigned long long)N_NODES) || (v1 >= (unsigned long long)N_NODES));
        if (threadIdx.x == 0) s_is64 = m ? 0 : 1;
    }
    __syncthreads();
    return s_is64;
}

// ---------------- prep: detect + pack edges + degree hist + zero smalls -----
__global__ void prep_kernel(const void* ei) {
    int is64 = detect_is64(ei);
    if (blockIdx.x == 0) {
        for (int i = threadIdx.x; i < N_GRAPHS; i += 256) {
            g_gsum[i] = 0.f; g_gcnt[i] = 0.f;
        }
        if (threadIdx.x == 0) g_done = 0;
    }
    int e = blockIdx.x * 256 + threadIdx.x;
    if (e >= N_EDGES) return;
    int s, d;
    if (is64) {
        const long long* p = (const long long*)ei;
        s = (int)p[e]; d = (int)p[N_EDGES + e];
    } else {
        const int* p = (const int*)ei;
        s = p[e]; d = p[N_EDGES + e];
    }
    s = min(max(s, 0), N_NODES - 1);
    d = min(max(d, 0), N_NODES - 1);
    g_edge[e] = (unsigned long long)(unsigned)s |
                ((unsigned long long)(unsigned)d << 32);
    atomicAdd(&g_degi[d], 1);
}

// ---------------- dis table: g_dish[n] = fp16(rsqrt(deg+1)) -----------------
__global__ void dis_kernel() {
    int i = blockIdx.x * 256 + threadIdx.x;
    if (i < N_NODES)
        g_dish[i] = __float2half(rsqrtf((float)g_degi[i] + 1.0f));
}

// ---------------- gemm1 (degree-free!): h1 = fp16(x@W1); zero agg1 ----------
__global__ __launch_bounds__(256) void gemm1_raw(const float* __restrict__ x,
                                                 const float* __restrict__ W) {
    constexpr int K = 128;
    constexpr int KT = 32;
    constexpr int NPAD = 264;
    __shared__ float Ws[K * 32];
    __shared__ float xs[KT * NPAD];

    int tid = threadIdx.x;
    for (int i = tid; i < K * 8; i += 256)
        ((float4*)Ws)[i] = ((const float4*)W)[i];

    int base = blockIdx.x * 256;
    int tx = tid & 3;
    int ty = tid >> 2;

    unsigned long long acc[4][4];
#pragma unroll
    for (int i = 0; i < 4; i++)
#pragma unroll
        for (int q = 0; q < 4; q++) acc[i][q] = 0ULL;

    int mync = min(base + tid, N_NODES - 1);

#pragma unroll
    for (int kt = 0; kt < K / KT; kt++) {
        const float4* row = (const float4*)(x + (size_t)mync * 128 + kt * KT);
#pragma unroll
        for (int j = 0; j < 8; j++) {
            float4 v = row[j];
            xs[(4 * j + 0) * NPAD + tid] = v.x;
            xs[(4 * j + 1) * NPAD + tid] = v.y;
            xs[(4 * j + 2) * NPAD + tid] = v.z;
            xs[(4 * j + 3) * NPAD + tid] = v.w;
        }
        __syncthreads();
#pragma unroll
        for (int k = 0; k < KT; k++) {
            float4 xv = *(const float4*)&xs[k * NPAD + ty * 4];
            const ulonglong2* wr = (const ulonglong2*)(Ws + (kt * KT + k) * 32 + tx * 8);
            ulonglong2 w0 = wr[0];
            ulonglong2 w1 = wr[1];
            unsigned long long xp0 = pack2(xv.x);
            unsigned long long xp1 = pack2(xv.y);
            unsigned long long xp2 = pack2(xv.z);
            unsigned long long xp3 = pack2(xv.w);
            ffma2(acc[0][0], xp0, w0.x); ffma2(acc[0][1], xp0, w0.y);
            ffma2(acc[0][2], xp0, w1.x); ffma2(acc[0][3], xp0, w1.y);
            ffma2(acc[1][0], xp1, w0.x); ffma2(acc[1][1], xp1, w0.y);
            ffma2(acc[1][2], xp1, w1.x); ffma2(acc[1][3], xp1, w1.y);
            ffma2(acc[2][0], xp2, w0.x); ffma2(acc[2][1], xp2, w0.y);
            ffma2(acc[2][2], xp2, w1.x); ffma2(acc[2][3], xp2, w1.y);
            ffma2(acc[3][0], xp3, w0.x); ffma2(acc[3][1], xp3, w0.y);
            ffma2(acc[3][2], xp3, w1.x); ffma2(acc[3][3], xp3, w1.y);
        }
        __syncthreads();
    }

#pragma unroll
    for (int i = 0; i < 4; i++) {
        int node = base + ty * 4 + i;
        if (node >= N_NODES) break;
        float2 p0 = unpack2(acc[i][0]);
        float2 p1 = unpack2(acc[i][1]);
        float2 p2 = unpack2(acc[i][2]);
        float2 p3 = unpack2(acc[i][3]);
        uint4 t;
        t.x = h2u(__floats2half2_rn(p0.x, p0.y));
        t.y = h2u(__floats2half2_rn(p1.x, p1.y));
        t.z = h2u(__floats2half2_rn(p2.x, p2.y));
        t.w = h2u(__floats2half2_rn(p3.x, p3.y));
        *(uint4*)(g_h1h + (size_t)node * 8 + tx * 2) = t;
        uint4 z; z.x = 0u; z.y = 0u; z.z = 0u; z.w = 0u;
        *(uint4*)(g_agg1h + (size_t)node * 8 + tx * 2) = z;
    }
}

// ---------------- gemm2: in = relu(dis*agg1 + dis^2*h1 + b1); h2'=(in@W2)*dis
__global__ __launch_bounds__(256) void gemm2_tiled(const float* __restrict__ W,
                                                   const float* __restrict__ b1) {
    constexpr int KT = 32;
    constexpr int NPAD = 264;
    __shared__ float Ws[32 * 32];
    __shared__ float xs[KT * NPAD];

    int tid = threadIdx.x;
    for (int i = tid; i < 32 * 8; i += 256)
        ((float4*)Ws)[i] = ((const float4*)W)[i];

    int base = blockIdx.x * 256;
    int tx = tid & 3;
    int ty = tid >> 2;

    unsigned long long acc[4][4];
#pragma unroll
    for (int i = 0; i < 4; i++)
#pragma unroll
        for (int q = 0; q < 4; q++) acc[i][q] = 0ULL;

    int mync = min(base + tid, N_NODES - 1);

    {
        float dis = rsqrtf((float)g_degi[mync] + 1.0f);
        float d2 = dis * dis;
        const uint2* aggp = g_agg1h + (size_t)mync * 8;
        const uint2* hp = g_h1h + (size_t)mync * 8;
#pragma unroll
        for (int cq = 0; cq < 8; cq++) {
            uint2 av = aggp[cq], hv = hp[cq];
            float2 a01 = u2f2(av.x), a23 = u2f2(av.y);
            float2 h01 = u2f2(hv.x), h23 = u2f2(hv.y);
            float4 b = ((const float4*)b1)[cq];
            xs[(4 * cq + 0) * NPAD + tid] = fmaxf(fmaf(dis, a01.x, fmaf(d2, h01.x, b.x)), 0.f);
            xs[(4 * cq + 1) * NPAD + tid] = fmaxf(fmaf(dis, a01.y, fmaf(d2, h01.y, b.y)), 0.f);
            xs[(4 * cq + 2) * NPAD + tid] = fmaxf(fmaf(dis, a23.x, fmaf(d2, h23.x, b.z)), 0.f);
            xs[(4 * cq + 3) * NPAD + tid] = fmaxf(fmaf(dis, a23.y, fmaf(d2, h23.y, b.w)), 0.f);
        }
    }
    __syncthreads();

#pragma unroll
    for (int k = 0; k < KT; k++) {
        float4 xv = *(const float4*)&xs[k * NPAD + ty * 4];
        const ulonglong2* wr = (const ulonglong2*)(Ws + k * 32 + tx * 8);
        ulonglong2 w0 = wr[0];
        ulonglong2 w1 = wr[1];
        unsigned long long xp0 = pack2(xv.x);
        unsigned long long xp1 = pack2(xv.y);
        unsigned long long xp2 = pack2(xv.z);
        unsigned long long xp3 = pack2(xv.w);
        ffma2(acc[0][0], xp0, w0.x); ffma2(acc[0][1], xp0, w0.y);
        ffma2(acc[0][2], xp0, w1.x); ffma2(acc[0][3], xp0, w1.y);
        ffma2(acc[1][0], xp1, w0.x); ffma2(acc[1][1], xp1, w0.y);
        ffma2(acc[1][2], xp1, w1.x); ffma2(acc[1][3], xp1, w1.y);
        ffma2(acc[2][0], xp2, w0.x); ffma2(acc[2][1], xp2, w0.y);
        ffma2(acc[2][2], xp2, w1.x); ffma2(acc[2][3], xp2, w1.y);
        ffma2(acc[3][0], xp3, w0.x); ffma2(acc[3][1], xp3, w0.y);
        ffma2(acc[3][2], xp3, w1.x); ffma2(acc[3][3], xp3, w1.y);
    }

#pragma unroll
    for (int i = 0; i < 4; i++) {
        int node = base + ty * 4 + i;
        if (node >= N_NODES) break;
        float dis = rsqrtf((float)g_degi[node] + 1.0f);
        float2 p0 = unpack2(acc[i][0]);
        float2 p1 = unpack2(acc[i][1]);
        float2 p2 = unpack2(acc[i][2]);
        float2 p3 = unpack2(acc[i][3]);
        uint4 t;
        t.x = h2u(__floats2half2_rn(p0.x * dis, p0.y * dis));
        t.y = h2u(__floats2half2_rn(p1.x * dis, p1.y * dis));
        t.z = h2u(__floats2half2_rn(p2.x * dis, p2.y * dis));
        t.w = h2u(__floats2half2_rn(p3.x * dis, p3.y * dis));
        *(uint4*)(g_h2h + (size_t)node * 8 + tx * 2) = t;
        uint4 z; z.x = 0u; z.y = 0u; z.z = 0u; z.w = 0u;
        *(uint4*)(g_agg2h + (size_t)node * 8 + tx * 2) = z;
    }
}

// ---------------- edge scatter: agg[dst] += h[src] (*dis[src] on layer 1) ----
// 4 lanes per edge (16B v4.f16x2 red); 4 independent edges/thread (MLP=4)
template <int LAYER>
__global__ __launch_bounds__(256) void scatter_kernel() {
    const uint4* h = (LAYER == 1) ? (const uint4*)g_h1h : (const uint4*)g_h2h;
    uint4* agg = (LAYER == 1) ? (uint4*)g_agg1h : (uint4*)g_agg2h;
    const int Q = N_EDGES / 4;

    int idx = blockIdx.x * 256 + threadIdx.x;
    int e0 = idx >> 2;
    if (e0 >= Q) return;
    int c = idx & 3;   // quarter-row: 16B = 1 uint4

    unsigned long long ed[4];
#pragma unroll
    for (int j = 0; j < 4; j++) ed[j] = g_edge[e0 + j * Q];

    uint4 v[4];
    __half2 dd[4];
#pragma unroll
    for (int j = 0; j < 4; j++) {
        unsigned s = (unsigned)(ed[j] & 0xffffffffu);
        v[j] = h[(size_t)s * 4 + c];
        if (LAYER == 1) dd[j] = __half2half2(g_dish[s]);
    }

    if (LAYER == 1) {
#pragma unroll
        for (int j = 0; j < 4; j++) {
            v[j].x = h2u(__hmul2(u2h2(v[j].x), dd[j]));
            v[j].y = h2u(__hmul2(u2h2(v[j].y), dd[j]));
            v[j].z = h2u(__hmul2(u2h2(v[j].z), dd[j]));
            v[j].w = h2u(__hmul2(u2h2(v[j].w), dd[j]));
        }
    }

#pragma unroll
    for (int j = 0; j < 4; j++) {
        uint4* p = agg + (size_t)(unsigned)(ed[j] >> 32) * 4 + c;
        asm volatile("red.global.add.noftz.v4.f16x2 [%0], {%1,%2,%3,%4};"
                     :: "l"(p), "r"(v[j].x), "r"(v[j].y), "r"(v[j].z), "r"(v[j].w)
                     : "memory");
    }
}

// ---------------- pool: relu2 + bias + dot(Wo) + segment sums + final -------
__global__ void pool_kernel(const void* ei, const void* batch,
                            const float* __restrict__ b2,
                            const float* __restrict__ Wo,
                            const float* __restrict__ bo,
                            float* __restrict__ out) {
    int is64 = detect_is64(ei);
    int n = blockIdx.x * 256 + threadIdx.x;
    if (n < N_NODES) {
        int g;
        if (is64) g = (int)((const long long*)batch)[n];
        else      g = ((const int*)batch)[n];
        g = min(max(g, 0), N_GRAPHS - 1);
        float dis = rsqrtf((float)g_degi[n] + 1.0f);
        const uint2* a2 = g_agg2h + (size_t)n * 8;
        const uint2* hh = g_h2h + (size_t)n * 8;
        float s = 0.f;
#pragma unroll
        for (int c = 0; c < 8; c++) {
            uint2 av = a2[c];
            uint2 hv = hh[c];
            float2 a01 = u2f2(av.x), a23 = u2f2(av.y);
            float2 h01 = u2f2(hv.x), h23 = u2f2(hv.y);
            float4 b = ((const float4*)b2)[c];
            float4 w = ((const float4*)Wo)[c];
            s += fmaxf(fmaf(dis, a01.x + h01.x, b.x), 0.f) * w.x;
            s += fmaxf(fmaf(dis, a01.y + h01.y, b.y), 0.f) * w.y;
            s += fmaxf(fmaf(dis, a23.x + h23.x, b.z), 0.f) * w.z;
            s += fmaxf(fmaf(dis, a23.y + h23.y, b.w), 0.f) * w.w;
        }
        atomicAdd(&g_gsum[g], s);
        atomicAdd(&g_gcnt[g], 1.0f);
    }

    // last-block finalize
    __threadfence();
    __syncthreads();
    __shared__ int s_last;
    if (threadIdx.x == 0) {
        int t = atomicAdd(&g_done, 1);
        s_last = (t == (int)gridDim.x - 1) ? 1 : 0;
    }
    __syncthreads();
    if (s_last) {
        float bias = bo[0];
        for (int i = threadIdx.x; i < N_GRAPHS; i += 256) {
            float sv = atomicAdd(&g_gsum[i], 0.0f);   // coherent read
            float cv = atomicAdd(&g_gcnt[i], 0.0f);
            out[i] = sv / fmaxf(cv, 1.0f) + bias;
        }
        __syncthreads();
        if (threadIdx.x == 0) g_done = 0;   // self-reset for graph replay
    }
}

// ---------------- launch ----------------------------------------------------
extern "C" void kernel_launch(void* const* d_in, const int* in_sizes, int n_in,
                              void* d_out, int out_size) {
    const float* x   = (const float*)d_in[0];
    const void*  ei  = d_in[1];
    const void*  bat = d_in[2];
    const float* W1  = (const float*)d_in[3];
    const float* b1  = (const float*)d_in[4];
    const float* W2  = (const float*)d_in[5];
    const float* b2  = (const float*)d_in[6];
    const float* Wo  = (const float*)d_in[7];
    const float* bo  = (const float*)d_in[8];
    float* out = (float*)d_out;

    // one-time resources (created on the eager correctness call, before capture)
    static cudaStream_t sB = nullptr;
    static cudaEvent_t evF = nullptr, evJ = nullptr;
    if (!sB) {
        cudaStreamCreateWithFlags(&sB, cudaStreamNonBlocking);
        cudaEventCreateWithFlags(&evF, cudaEventDisableTiming);
        cudaEventCreateWithFlags(&evJ, cudaEventDisableTiming);
    }

    void* p_degi = nullptr;
    cudaGetSymbolAddress(&p_degi, g_degi);

    const int GB = (N_NODES + 255) / 256;   // 391

    // fork: gemm1 (degree-free) runs concurrently with memset+prep+dis
    cudaEventRecord(evF, 0);
    cudaStreamWaitEvent(sB, evF, 0);
    gemm1_raw<<<GB, 256, 0, sB>>>(x, W1);

    cudaMemsetAsync(p_degi, 0, N_NODES * sizeof(int));
    prep_kernel<<<(N_EDGES + 255) / 256, 256>>>(ei);
    dis_kernel<<<GB, 256>>>();

    // join
    cudaEventRecord(evJ, sB);
    cudaStreamWaitEvent(0, evJ, 0);

    // layer 1 scatter (applies dis[src] from table)
    scatter_kernel<1><<<(N_EDGES + 255) / 256, 256>>>();

    // layer 2
    gemm2_tiled<<<GB, 256>>>(W2, b1);
    scatter_kernel<2><<<(N_EDGES + 255) / 256, 256>>>();

    // pooling + head (final fold via last-block)
    pool_kernel<<<(N_NODES + 255) / 256, 256>>>(ei, bat, b2, Wo, bo, out);
}